// round 1
// baseline (speedup 1.0000x reference)
#include <cuda_runtime.h>

#define B_ 8
#define T_ 2048
#define D_ 1024
#define H_ 64

// Scratch for projected Q (pre-scaled by 1/sqrt(HS)), K, V.  4 MB each.
__device__ float g_Q[B_ * T_ * H_];
__device__ float g_K[B_ * T_ * H_];
__device__ float g_V[B_ * T_ * H_];

// ---------------------------------------------------------------------------
// Kernel 1: fused QKV projection.  grid = (M/64, 3), block = 256.
// Tile: BM=64 rows x BN=64 cols (full HS), BK=32.  4x4 microtile per thread.
// blockIdx.y selects which of Q/K/V this block computes.
// Q is pre-scaled by 0.125 = 1/sqrt(64); mask-before-scale in the reference is
// equivalent since -inf is scale invariant.
// ---------------------------------------------------------------------------
__global__ __launch_bounds__(256) void qkv_proj_kernel(
    const float* __restrict__ x,
    const float* __restrict__ Wq, const float* __restrict__ bq,
    const float* __restrict__ Wk, const float* __restrict__ bk,
    const float* __restrict__ Wv, const float* __restrict__ bv)
{
    __shared__ float xs[64][33];   // x tile, padded (scalar access, conflict-free)
    __shared__ float ws[32][64];   // W tile

    const float* W;
    const float* bias;
    float* out;
    float scale;
    if (blockIdx.y == 0)      { W = Wq; bias = bq; out = g_Q; scale = 0.125f; }
    else if (blockIdx.y == 1) { W = Wk; bias = bk; out = g_K; scale = 1.0f;   }
    else                      { W = Wv; bias = bv; out = g_V; scale = 1.0f;   }

    const int tid = threadIdx.x;
    const int tx  = tid & 15;   // 0..15 -> output cols tx*4..tx*4+3
    const int ty  = tid >> 4;   // 0..15 -> output rows ty*4..ty*4+3
    const int m0  = blockIdx.x * 64;

    float acc[4][4] = {};

    for (int k0 = 0; k0 < D_; k0 += 32) {
        // load x tile [64 x 32], 2 float4 per thread, coalesced
        #pragma unroll
        for (int l = 0; l < 2; l++) {
            int lin = tid * 8 + l * 4;      // 0..2044 step 4
            int i = lin >> 5, k = lin & 31;
            float4 v = *(const float4*)(x + (size_t)(m0 + i) * D_ + k0 + k);
            xs[i][k + 0] = v.x; xs[i][k + 1] = v.y;
            xs[i][k + 2] = v.z; xs[i][k + 3] = v.w;
        }
        // load W tile [32 x 64], 2 float4 per thread, coalesced
        #pragma unroll
        for (int l = 0; l < 2; l++) {
            int lin = tid * 8 + l * 4;
            int kr = lin >> 6, c = lin & 63;
            *(float4*)&ws[kr][c] = *(const float4*)(W + (size_t)(k0 + kr) * H_ + c);
        }
        __syncthreads();

        #pragma unroll
        for (int kk = 0; kk < 32; kk++) {
            float a0 = xs[ty * 4 + 0][kk];
            float a1 = xs[ty * 4 + 1][kk];
            float a2 = xs[ty * 4 + 2][kk];
            float a3 = xs[ty * 4 + 3][kk];
            float4 b4 = *(float4*)&ws[kk][tx * 4];
            acc[0][0] += a0 * b4.x; acc[0][1] += a0 * b4.y; acc[0][2] += a0 * b4.z; acc[0][3] += a0 * b4.w;
            acc[1][0] += a1 * b4.x; acc[1][1] += a1 * b4.y; acc[1][2] += a1 * b4.z; acc[1][3] += a1 * b4.w;
            acc[2][0] += a2 * b4.x; acc[2][1] += a2 * b4.y; acc[2][2] += a2 * b4.z; acc[2][3] += a2 * b4.w;
            acc[3][0] += a3 * b4.x; acc[3][1] += a3 * b4.y; acc[3][2] += a3 * b4.z; acc[3][3] += a3 * b4.w;
        }
        __syncthreads();
    }

    #pragma unroll
    for (int i = 0; i < 4; i++) {
        #pragma unroll
        for (int j = 0; j < 4; j++) {
            float bb = bias[tx * 4 + j];
            out[(size_t)(m0 + ty * 4 + i) * H_ + tx * 4 + j] = (acc[i][j] + bb) * scale;
        }
    }
}

// ---------------------------------------------------------------------------
// Kernel 2: causal flash attention, fp32.
// grid = (T/64, B), block = 64 threads.  Thread r owns q-row (qblk*64 + r):
// q[64] and o[64] live in registers; K/V tiles (64 keys) staged in smem and
// consumed as broadcast LDS.128 (1 smem load per 4 FMAs -> FFMA-bound).
// Online softmax in chunks of 8 keys.  Mask applied only on diagonal tile.
// ---------------------------------------------------------------------------
__global__ __launch_bounds__(64) void attn_kernel(float* __restrict__ out)
{
    __shared__ float Ks[64][64];
    __shared__ float Vs[64][64];

    const int r    = threadIdx.x;
    const int qblk = blockIdx.x;
    const int b    = blockIdx.y;
    const int qrow = qblk * 64 + r;

    // load this thread's (pre-scaled) q row into registers
    float q[64];
    {
        const float* Qrow = g_Q + ((size_t)b * T_ + qrow) * H_;
        #pragma unroll
        for (int d4 = 0; d4 < 16; d4++) {
            float4 v = *(const float4*)(Qrow + d4 * 4);
            q[d4 * 4 + 0] = v.x; q[d4 * 4 + 1] = v.y;
            q[d4 * 4 + 2] = v.z; q[d4 * 4 + 3] = v.w;
        }
    }

    float o[64];
    #pragma unroll
    for (int d = 0; d < 64; d++) o[d] = 0.0f;
    float m = -1e30f;
    float l = 0.0f;

    const int ntiles = qblk + 1;   // causal: only kv tiles 0..qblk
    for (int t = 0; t < ntiles; t++) {
        // cooperatively load K/V tile (64 keys x 64 dims), coalesced
        {
            const float* Kt = g_K + ((size_t)b * T_ + t * 64) * H_;
            const float* Vt = g_V + ((size_t)b * T_ + t * 64) * H_;
            float* ksf = &Ks[0][0];
            float* vsf = &Vs[0][0];
            #pragma unroll
            for (int l2 = 0; l2 < 16; l2++) {
                int lin = l2 * 256 + r * 4;
                *(float4*)(ksf + lin) = *(const float4*)(Kt + lin);
                *(float4*)(vsf + lin) = *(const float4*)(Vt + lin);
            }
        }
        __syncthreads();

        const bool diag = (t == qblk);

        #pragma unroll 1
        for (int c = 0; c < 8; c++) {          // 8 chunks of 8 keys
            float s[8];
            #pragma unroll
            for (int j = 0; j < 8; j++) {
                float acc = 0.0f;
                #pragma unroll
                for (int d4 = 0; d4 < 16; d4++) {
                    float4 kv = *(const float4*)&Ks[c * 8 + j][d4 * 4];
                    acc += q[d4 * 4 + 0] * kv.x;
                    acc += q[d4 * 4 + 1] * kv.y;
                    acc += q[d4 * 4 + 2] * kv.z;
                    acc += q[d4 * 4 + 3] * kv.w;
                }
                s[j] = acc;
            }
            if (diag) {
                #pragma unroll
                for (int j = 0; j < 8; j++)
                    if (t * 64 + c * 8 + j > qrow) s[j] = -1e30f;
            }
            float mloc = m;
            #pragma unroll
            for (int j = 0; j < 8; j++) mloc = fmaxf(mloc, s[j]);
            float alpha = __expf(m - mloc);
            m = mloc;
            l *= alpha;
            #pragma unroll
            for (int d = 0; d < 64; d++) o[d] *= alpha;
            #pragma unroll
            for (int j = 0; j < 8; j++) {
                float p = __expf(s[j] - m);
                l += p;
                #pragma unroll
                for (int d4 = 0; d4 < 16; d4++) {
                    float4 vv = *(const float4*)&Vs[c * 8 + j][d4 * 4];
                    o[d4 * 4 + 0] += p * vv.x;
                    o[d4 * 4 + 1] += p * vv.y;
                    o[d4 * 4 + 2] += p * vv.z;
                    o[d4 * 4 + 3] += p * vv.w;
                }
            }
        }
        __syncthreads();
    }

    const float inv_l = 1.0f / l;
    float* orow = out + ((size_t)b * T_ + qrow) * H_;
    #pragma unroll
    for (int d4 = 0; d4 < 16; d4++) {
        float4 v;
        v.x = o[d4 * 4 + 0] * inv_l;
        v.y = o[d4 * 4 + 1] * inv_l;
        v.z = o[d4 * 4 + 2] * inv_l;
        v.w = o[d4 * 4 + 3] * inv_l;
        *(float4*)(orow + d4 * 4) = v;
    }
}

// ---------------------------------------------------------------------------
extern "C" void kernel_launch(void* const* d_in, const int* in_sizes, int n_in,
                              void* d_out, int out_size)
{
    const float* x  = (const float*)d_in[0];
    const float* Wq = (const float*)d_in[1];
    const float* bq = (const float*)d_in[2];
    const float* Wk = (const float*)d_in[3];
    const float* bk = (const float*)d_in[4];
    const float* Wv = (const float*)d_in[5];
    const float* bv = (const float*)d_in[6];
    float* out = (float*)d_out;

    qkv_proj_kernel<<<dim3((B_ * T_) / 64, 3), 256>>>(x, Wq, bq, Wk, bk, Wv, bv);
    attn_kernel<<<dim3(T_ / 64, B_), 64>>>(out);
}